// round 17
// baseline (speedup 1.0000x reference)
#include <cuda_runtime.h>
#include <cstdint>

#define N_TOK   4096
#define C_DIM   64
#define HW      256
#define E_EXP   16
#define CCAP    384
#define PLANE   (E_EXP * CCAP)             /* 6144 */
#define HALF    ((long long)N_TOK * PLANE) /* 25,165,824 floats */
#define NBIN    32

// ---------------- device scratch (reset each replay by the finisher) ----------------
__device__ float g_gate[N_TOK];
__device__ int   g_arg[N_TOK];
__device__ float g_psumb[NBIN * E_EXP];   // binned prob sums (bin-major)
__device__ float g_zsumb[NBIN];           // binned lse sums
__device__ int   g_done;                  // completed pool blocks

// =====================================================================
// Single compute kernel. grid = 4096 x 512. Pure-read pool with
// distributed matvec (R16); the LAST block to finish becomes the
// finisher (R12 scan/scatter) — no polling, no extra kernel node.
// =====================================================================
__global__ void __launch_bounds__(512, 4)
k_pool(const float* __restrict__ X, const float* __restrict__ Wg,
       const float* __restrict__ bg, float* __restrict__ out) {
    const int n    = blockIdx.x;
    const int tid  = threadIdx.x;
    const int w    = tid >> 5;
    const int lane = tid & 31;

    __shared__ union {
        float part[16][E_EXP];                 // pool phase
        struct {                               // finisher phase (aliased)
            int            arg[N_TOK];         // 16 KB
            unsigned short rank[N_TOK];        //  8 KB
            int   cnt[16][E_EXP + 1];
            int   off[16][E_EXP + 1];
            int   tot[E_EXP];
            float psum[E_EXP];
            float z;
        } fin;
    } sm;
    __shared__ int s_last;

    // ---- preload this warp's W slice into registers (lanes 0-15) ----
    float wreg0 = 0.f, wreg1 = 0.f, wreg2 = 0.f, wreg3 = 0.f;
    if (lane < E_EXP) {
        const float* wr = Wg + (4 * w) * E_EXP + lane;
        wreg0 = wr[0 * E_EXP];
        wreg1 = wr[1 * E_EXP];
        wreg2 = wr[2 * E_EXP];
        wreg3 = wr[3 * E_EXP];
    }

    // ---- coalesced streaming read; warp w owns channels [4w, 4w+4) ----
    const float4* p = reinterpret_cast<const float4*>(X + (size_t)n * C_DIM * HW)
                      + w * 256;
    float part[4] = {0.f, 0.f, 0.f, 0.f};
#pragma unroll
    for (int k = 0; k < 8; k++) {
        float4 v = __ldcs(p + lane + 32 * k);       // lanes consecutive -> coalesced
        part[k >> 1] += (v.x + v.y) + (v.z + v.w);
    }

    // butterfly reduce -> all lanes hold each channel mean
#pragma unroll
    for (int c = 0; c < 4; c++) {
        float s = part[c];
#pragma unroll
        for (int off = 16; off; off >>= 1) s += __shfl_xor_sync(0xffffffffu, s, off);
        part[c] = s * (1.0f / HW);
    }

    // lanes 0-15: this warp's partial logit for expert `lane`
    if (lane < E_EXP) {
        sm.part[w][lane] = part[0] * wreg0 + part[1] * wreg1
                         + part[2] * wreg2 + part[3] * wreg3;
    }
    __syncthreads();

    // ---- warp 0: final logits + softmax + argmax + signal ----
    if (w == 0) {
        float l = -INFINITY;
        if (lane < E_EXP) {
            float acc = bg[lane];
#pragma unroll
            for (int ww = 0; ww < 16; ww++) acc += sm.part[ww][lane];
            l = acc;
        }
        float mx = l;
#pragma unroll
        for (int off = 16; off; off >>= 1) mx = fmaxf(mx, __shfl_xor_sync(0xffffffffu, mx, off));
        float e = (lane < E_EXP) ? __expf(l - mx) : 0.f;
        float s = e;
#pragma unroll
        for (int off = 16; off; off >>= 1) s += __shfl_xor_sync(0xffffffffu, s, off);
        float prob = e / s;
        float lse  = mx + __logf(s);

        unsigned bal = __ballot_sync(0xffffffffu, l == mx);
        int arg = __ffs(bal) - 1;                   // lowest-index max == jnp argmax
        float gate = __shfl_sync(0xffffffffu, prob, arg);

        const int bin = n & (NBIN - 1);             // binned: no line contention
        if (lane < E_EXP) atomicAdd(&g_psumb[bin * E_EXP + lane], prob);
        if (lane == 0) {
            g_gate[n] = gate;
            g_arg[n]  = arg;
            atomicAdd(&g_zsumb[bin], lse);
            __threadfence();                        // release token-n writes
            int old = atomicAdd(&g_done, 1);
            s_last = (old == N_TOK - 1);
        }
    }
    __syncthreads();
    if (!s_last) return;

    // ================= finisher (exactly one block, hot L2) =================
    __threadfence();                                // acquire side
    __syncthreads();                                // before aliasing sm.part

    // phase 0: bulk coalesced prefetch of g_arg
    {
        const int4* pa = reinterpret_cast<const int4*>(g_arg);
#pragma unroll
        for (int r = 0; r < 2; r++) {
            int i = tid + r * 512;
            reinterpret_cast<int4*>(sm.fin.arg)[i] = pa[i];
        }
    }
    __syncthreads();

    // phase A: per-chunk expert ranks (warp w owns tokens [256w, 256w+256))
    if (lane <= E_EXP) sm.fin.cnt[w][lane] = 0;
    __syncwarp();
#pragma unroll
    for (int g = 0; g < 8; g++) {
        int t = 256 * w + 32 * g + lane;
        int a = sm.fin.arg[t];
        unsigned m = __match_any_sync(0xffffffffu, a);
        int prior = sm.fin.cnt[w][a];
        __syncwarp();
        if (lane == (int)__ffs(m) - 1) sm.fin.cnt[w][a] = prior + __popc(m);
        sm.fin.rank[t] = (unsigned short)(prior + __popc(m & ((1u << lane) - 1u)));
        __syncwarp();
    }
    __syncthreads();

    // phase B: exclusive prefix over 16 chunks (warp w = expert w)
    if (lane < 16) {
        int v = sm.fin.cnt[lane][w];
        int x = v;
#pragma unroll
        for (int off = 1; off < 16; off <<= 1) {
            int y = __shfl_up_sync(0x0000ffffu, x, off);
            if (lane >= off) x += y;
        }
        sm.fin.off[lane][w] = x - v;
        if (lane == 15) sm.fin.tot[w] = x;
    }
    if (tid < E_EXP) sm.fin.psum[tid] = 0.f;
    if (tid == 0)    sm.fin.z = 0.f;
    __syncthreads();

    // phase C: scatter all 4096 nonzero pairs (8 tokens per thread)
#pragma unroll
    for (int rep = 0; rep < 8; rep++) {
        int t = tid + rep * 512;
        int a = sm.fin.arg[t];
        int pos = sm.fin.off[t >> 8][a] + (int)sm.fin.rank[t];
        if (pos < CCAP) {
            long long off = (long long)t * PLANE + a * CCAP + pos;
            float gate = g_gate[t];                 // L2-hit
            __stcs(out + off, 1.0f);                // dispatch
            __stcs(out + HALF + off, gate);         // combine
        }
    }

    // binned loss sums -> shared (+ reset bins for next replay)
    {
        float v = g_psumb[tid];                     // 512 = NBIN*E_EXP exactly
        g_psumb[tid] = 0.f;
        atomicAdd(&sm.fin.psum[tid & (E_EXP - 1)], v);
        if (tid < NBIN) {
            float z = g_zsumb[tid];
            g_zsumb[tid] = 0.f;
            atomicAdd(&sm.fin.z, z);
        }
    }
    __syncthreads();

    // scalars + counter reset
    if (tid == 0) {
        float aux = 0.f;
#pragma unroll
        for (int e = 0; e < E_EXP; e++) aux += sm.fin.psum[e] * (float)sm.fin.tot[e];
        const float invN = 1.0f / (float)N_TOK;
        out[2 * HALF]     = sm.fin.z * invN;                     // z_loss
        out[2 * HALF + 1] = aux * (float)E_EXP * invN * invN;    // aux_loss
        __threadfence();
        g_done = 0;
    }
}

// ---------------- launch ----------------
extern "C" void kernel_launch(void* const* d_in, const int* in_sizes, int n_in,
                              void* d_out, int out_size) {
    const float* X  = (const float*)d_in[0];
    const float* Wg = (const float*)d_in[1];
    const float* bg = (const float*)d_in[2];
    float* out = (float*)d_out;

    // driver memset node: pure-write zero-fill of both output planes
    cudaMemsetAsync(out, 0, (size_t)(2 * HALF) * sizeof(float));

    k_pool<<<N_TOK, 512>>>(X, Wg, bg, out);  // pure-read + last-block finisher
}